// round 16
// baseline (speedup 1.0000x reference)
#include <cuda_runtime.h>
#include <cuda_fp16.h>
#include <cstdint>

// ============================================================================
// BinaryConv2D: x(64,56,56,128) NHWC conv w(3,3,128,256) HWIO, SAME, stride 1.
// binarize both -> implicit GEMM on mma.sync m16n8k32 e4m3, F16 accumulate
// (exact: products ±1, partial sums are integers <= 1152 < 2048).
// == R16: raise MMA fraction of the issue stream 57% -> 67% ==
// Warps re-split 1M x 8N: warp tile 64px x 32oc (mi=4, ni=4), inner step
// per-kp: 4 LDSM + 4 LDG.64 + 16 MMA = 24 instrs. Live regs DROP (~70):
// acc 32 + a 16 (one kp at a time) + bv 2. L1 wavefronts/CTA unchanged.
// CTA: 64 px (8h x 8w, zero waste 56=7x8) x 256 outch, 256 thr, 3 CTAs/SM.
//   A: SMEM halo 10x10 px (14.4KB), padded-linear 144B rows, loaded once.
//   B: no smem; fragment-ordered uint2 = one k-step {b0,b1}, __ldg right
//      before use (short live ranges; R9: batching => spills).
// Rate-pin context: tensor% == MMA fraction of issued instrs (57%) across
// 9 variants -> this round tests the issue-mix hypothesis directly.
// (tcgen05/TMEM unavailable: harness ptxas targets base sm_103 — proven R1.)
// ============================================================================

constexpr int X_ELEMS = 64 * 56 * 56 * 128;   // 25,690,112
constexpr int WF_U2   = 9 * 4 * 32 * 32;      // 36,864 uint2 = 294,912 B
constexpr int X_BLOCKS = X_ELEMS / 8 / 256;   // 12,544

__device__ uint8_t g_xq[X_ELEMS];             // binarized x, NHWC e4m3
__device__ uint2   g_wf[WF_U2];               // weights, fragment-ordered

// ---------------------------------------------------------------------------
// merged preprocessing: e4m3 +1.0 = 0x38, -1.0 = 0xB8
// ---------------------------------------------------------------------------
__global__ void prep_kernel(const float* __restrict__ x,
                            const float* __restrict__ w) {
    if (blockIdx.x < X_BLOCKS) {
        int t = blockIdx.x * 256 + threadIdx.x;
        int base = t * 8;
        const float4* p = reinterpret_cast<const float4*>(x + base);
        float4 v0 = p[0], v1 = p[1];
        uint32_t lo = (v0.x >= 0.0f ? 0x38u : 0xB8u)        |
                      ((v0.y >= 0.0f ? 0x38u : 0xB8u) << 8)  |
                      ((v0.z >= 0.0f ? 0x38u : 0xB8u) << 16) |
                      ((v0.w >= 0.0f ? 0x38u : 0xB8u) << 24);
        uint32_t hi = (v1.x >= 0.0f ? 0x38u : 0xB8u)        |
                      ((v1.y >= 0.0f ? 0x38u : 0xB8u) << 8)  |
                      ((v1.z >= 0.0f ? 0x38u : 0xB8u) << 16) |
                      ((v1.w >= 0.0f ? 0x38u : 0xB8u) << 24);
        *reinterpret_cast<uint2*>(g_xq + base) = make_uint2(lo, hi);
    } else {
        // fragment order: u2 = ((tap*4 + k)*32 + g)*32 + lane
        //   outch o = g*8 + (lane>>2),  g = 0..31 covers all 256 outch
        //   {x,y} = B-frag regs (b0,b1) for k-step k (m16n8k32 colB)
        //   b0 bytes b2: ch = k*32 + (lane&3)*4 + b2 ; b1: +16
        int u = (blockIdx.x - X_BLOCKS) * 256 + threadIdx.x;
        if (u >= WF_U2) return;
        int lane = u & 31;
        int g    = (u >> 5) & 31;
        int k    = (u >> 10) & 3;
        int tap  = u >> 12;
        int o  = g * 8 + (lane >> 2);
        int cb = k * 32 + (lane & 3) * 4;
        uint32_t r0 = 0, r1 = 0;
        #pragma unroll
        for (int b2 = 0; b2 < 4; ++b2) {
            float v0 = w[(tap * 128 + cb + b2) * 256 + o];       // HWIO
            float v1 = w[(tap * 128 + cb + 16 + b2) * 256 + o];
            r0 |= (v0 >= 0.0f ? 0x38u : 0xB8u) << (8 * b2);
            r1 |= (v1 >= 0.0f ? 0x38u : 0xB8u) << (8 * b2);
        }
        g_wf[u] = make_uint2(r0, r1);
    }
}

// ---------------------------------------------------------------------------
// PTX helpers
// ---------------------------------------------------------------------------
static __device__ __forceinline__ void ldmatrix_x4(uint32_t& r0, uint32_t& r1,
                                                   uint32_t& r2, uint32_t& r3,
                                                   uint32_t addr) {
    asm volatile("ldmatrix.sync.aligned.m8n8.x4.shared.b16 {%0,%1,%2,%3}, [%4];"
                 : "=r"(r0), "=r"(r1), "=r"(r2), "=r"(r3) : "r"(addr));
}

// fp8 MMA with f16 accumulators (2 regs, exact for integer sums < 2048)
static __device__ __forceinline__ void mma_fp8_h(uint32_t* c, const uint32_t* a,
                                                 uint32_t b0, uint32_t b1) {
    asm volatile(
        "mma.sync.aligned.m16n8k32.row.col.f16.e4m3.e4m3.f16 "
        "{%0,%1}, {%2,%3,%4,%5}, {%6,%7}, {%0,%1};"
        : "+r"(c[0]), "+r"(c[1])
        : "r"(a[0]), "r"(a[1]), "r"(a[2]), "r"(a[3]), "r"(b0), "r"(b1));
}

static __device__ __forceinline__ void cp16(uint32_t dst, const void* src, int srcsize) {
    asm volatile("cp.async.cg.shared.global [%0], [%1], 16, %2;"
                 :: "r"(dst), "l"(src), "r"(srcsize) : "memory");
}

// ---------------------------------------------------------------------------
// main kernel: 256 threads, 8 warps (1M x 8N), warp tile 64px x 32oc
// SMEM: A halo only, 100 rows x 144B stride = 14,400 B
// ---------------------------------------------------------------------------
constexpr int ROWB = 144;
constexpr int SMEM_TOTAL = 100 * ROWB;        // 14,400

__global__ void __launch_bounds__(256, 3)
conv_fp8_kernel(float* __restrict__ out) {
    extern __shared__ char smem[];
    uint32_t sbase = (uint32_t)__cvta_generic_to_shared(smem);

    int tid  = threadIdx.x;
    int lane = tid & 31;
    int warp_n = tid >> 5;       // 0..7 -> 32 outch each (all warps see all M)

    // tile decode: blockIdx = img*49 + ht*7 + wt   (zero-waste 8x8 tiles)
    int b = blockIdx.x;
    int img = b / 49;
    int rr  = b - img * 49;
    int ht  = rr / 7;
    int wt  = rr - ht * 7;
    int h0 = ht * 8;
    int w0 = wt * 8;

    // ---- stage A halo (10h x 10w pixels, zero-filled outside image) ----
    for (int idx = tid; idx < 800; idx += 256) {         // 100 rows x 8 chunks
        int row = idx >> 3, ch = idx & 7;
        int hr = row / 10;
        int wc = row - hr * 10;
        int hh = h0 + hr - 1;
        int ww = w0 + wc - 1;
        bool v = ((unsigned)hh < 56u) && ((unsigned)ww < 56u);
        const char* src = v ? (const char*)(g_xq + (((img * 56 + hh) * 56 + ww) << 7))
                            : (const char*)g_xq;
        cp16(sbase + row * ROWB + ch * 16, src + ch * 16, v ? 16 : 0);
    }
    asm volatile("cp.async.commit_group;" ::: "memory");
    asm volatile("cp.async.wait_group 0;" ::: "memory");
    __syncthreads();

    // ---- per-lane ldmatrix base addresses (linear, conflict-free) ----
    int lane15 = lane & 15;
    int lanehi = lane >> 4;
    uint32_t abase[4];
    #pragma unroll
    for (int mi = 0; mi < 4; ++mi) {
        int p = mi * 16 + lane15;                        // pixel index 0..63
        int hrow = (p >> 3) * 10 + (p & 7);              // halo row at tap (0,0)
        abase[mi] = sbase + hrow * ROWB + lanehi * 16;
    }
    // B fragment base for this thread: g = warp_n*4 + ni
    const uint2* wf0 = g_wf + (uint32_t)((warp_n * 4) * 32 + lane);

    uint32_t acc[4][4][2];                               // f16x2 accumulators
    #pragma unroll
    for (int mi = 0; mi < 4; ++mi)
        #pragma unroll
        for (int ni = 0; ni < 4; ++ni) {
            acc[mi][ni][0] = 0u; acc[mi][ni][1] = 0u;
        }

    // ---- mainloop: kh x3 (rolled), kw x3 + k x4 fully unrolled ----
    // per k-step: 4 LDSM + 4 LDG.64 + 16 MMA  (67% MMA issue mix)
    for (int kh = 0; kh < 3; ++kh) {
        uint32_t akh0 = abase[0] + (uint32_t)(kh * 10 * ROWB);
        uint32_t akh1 = abase[1] + (uint32_t)(kh * 10 * ROWB);
        uint32_t akh2 = abase[2] + (uint32_t)(kh * 10 * ROWB);
        uint32_t akh3 = abase[3] + (uint32_t)(kh * 10 * ROWB);
        const uint2* wkh = wf0 + (uint32_t)(kh * 3 * 4096);  // 3 taps * 4k*1024
        #pragma unroll
        for (int kw = 0; kw < 3; ++kw) {
            #pragma unroll
            for (int k = 0; k < 4; ++k) {
                uint32_t koff = (uint32_t)(kw * ROWB + k * 32);
                uint32_t a[4][4];
                ldmatrix_x4(a[0][0], a[0][1], a[0][2], a[0][3], akh0 + koff);
                ldmatrix_x4(a[1][0], a[1][1], a[1][2], a[1][3], akh1 + koff);
                ldmatrix_x4(a[2][0], a[2][1], a[2][2], a[2][3], akh2 + koff);
                ldmatrix_x4(a[3][0], a[3][1], a[3][2], a[3][3], akh3 + koff);
                const uint2* wfk = wkh + (uint32_t)((kw * 4 + k) * 1024);
                #pragma unroll
                for (int ni = 0; ni < 4; ++ni) {
                    uint2 bv = __ldg(wfk + ni * 32);      // g stride = 32 u2
                    mma_fp8_h(acc[0][ni], a[0], bv.x, bv.y);
                    mma_fp8_h(acc[1][ni], a[1], bv.x, bv.y);
                    mma_fp8_h(acc[2][ni], a[2], bv.x, bv.y);
                    mma_fp8_h(acc[3][ni], a[3], bv.x, bv.y);
                }
            }
        }
    }

    // ---- epilogue: f16x2 -> f32 stores (exact; all 64 px in-image) ----
    int colbase = warp_n * 32 + (lane & 3) * 2;
    #pragma unroll
    for (int mi = 0; mi < 4; ++mi) {
        #pragma unroll
        for (int half = 0; half < 2; ++half) {
            int p = mi * 16 + half * 8 + (lane >> 2);
            int hh = h0 + (p >> 3);
            int ww = w0 + (p & 7);
            float* op = out + (((img * 56 + hh) * 56 + ww) << 8);
            #pragma unroll
            for (int ni = 0; ni < 4; ++ni) {
                __half2 h = *reinterpret_cast<__half2*>(&acc[mi][ni][half]);
                float2 v = __half22float2(h);
                *reinterpret_cast<float2*>(op + colbase + ni * 8) = v;
            }
        }
    }
}

// ---------------------------------------------------------------------------
// launch
// ---------------------------------------------------------------------------
extern "C" void kernel_launch(void* const* d_in, const int* in_sizes, int n_in,
                              void* d_out, int out_size) {
    const float* x = (const float*)d_in[0];
    const float* w = (const float*)d_in[1];
    float* out = (float*)d_out;

    prep_kernel<<<X_BLOCKS + (WF_U2 + 255) / 256, 256>>>(x, w);

    cudaFuncSetAttribute(conv_fp8_kernel,
                         cudaFuncAttributeMaxDynamicSharedMemorySize, SMEM_TOTAL);
    // 64 images * 7 h-tiles * 7 w-tiles = 3136 CTAs (zero wasted MMAs)
    conv_fp8_kernel<<<3136, 256, SMEM_TOTAL>>>(out);
}